// round 1
// baseline (speedup 1.0000x reference)
#include <cuda_runtime.h>

#define NN 100000
#define EE 800000
#define INC 64
#define HH 128
#define KK 9
#define FULL 0xffffffffu

#define OFF_OUT 0
#define OFF_MC  1152
#define OFF_O   1153
#define OFF_S   1154
#define OFF_OA  901154

// Scratch (static device globals — allocation-free)
__device__ __align__(16) float g_h[NN * HH];    // x @ W1
__device__ __align__(16) float g_agg[NN * HH];  // GCN aggregation
__device__ float g_deg[NN];                     // in-degree (no self loop)
__device__ float g_dinv[NN];
__device__ float g_xpool[KK * HH];
__device__ float g_outadj[KK * KK];
__device__ float g_ss[KK * KK];
__device__ float g_den[1];

// ---------------------------------------------------------------------------
// Zero accumulators (must run every call — graph replays)
// ---------------------------------------------------------------------------
__global__ void k_zero() {
    int i = blockIdx.x * blockDim.x + threadIdx.x;
    if (i < NN) g_deg[i] = 0.f;
    if (i < KK * HH) g_xpool[i] = 0.f;
    if (i < KK * KK) { g_outadj[i] = 0.f; g_ss[i] = 0.f; }
    if (i == 0) g_den[0] = 0.f;
}

// ---------------------------------------------------------------------------
// h = x @ W1   (N x 64 @ 64 x 128). W1 staged in smem, warp per row.
// ---------------------------------------------------------------------------
__global__ void k_gemm1(const float* __restrict__ x, const float* __restrict__ W1) {
    __shared__ float Ws[INC * HH];  // 32 KB
    for (int i = threadIdx.x; i < INC * HH; i += blockDim.x) Ws[i] = W1[i];
    __syncthreads();
    const int lane = threadIdx.x & 31, warp = threadIdx.x >> 5;
    const int nw = (blockDim.x >> 5) * gridDim.x;
    for (int n = blockIdx.x * (blockDim.x >> 5) + warp; n < NN; n += nw) {
        float xv0 = x[(size_t)n * INC + lane];
        float xv1 = x[(size_t)n * INC + 32 + lane];
        float a0 = 0.f, a1 = 0.f, a2 = 0.f, a3 = 0.f;
#pragma unroll
        for (int k = 0; k < INC; k++) {
            float xk = __shfl_sync(FULL, (k < 32) ? xv0 : xv1, k & 31);
            const float* w = Ws + k * HH + lane;
            a0 += xk * w[0]; a1 += xk * w[32]; a2 += xk * w[64]; a3 += xk * w[96];
        }
        float* hp = g_h + (size_t)n * HH + lane;
        hp[0] = a0; hp[32] = a1; hp[64] = a2; hp[96] = a3;
    }
}

// ---------------------------------------------------------------------------
// In-degree at dst (no self loops)
// ---------------------------------------------------------------------------
__global__ void k_deg(const int* __restrict__ dst) {
    int e = blockIdx.x * blockDim.x + threadIdx.x;
    if (e < EE) atomicAdd(&g_deg[dst[e]], 1.0f);
}

// ---------------------------------------------------------------------------
// dinv = rsqrt(deg+1); agg = dinv^2 * h   (self-loop term)
// ---------------------------------------------------------------------------
__global__ void k_init() {
    int i = blockIdx.x * blockDim.x + threadIdx.x;  // float4 index
    if (i >= NN * HH / 4) return;
    int n = i >> 5;  // 32 float4 per row
    float di = rsqrtf(g_deg[n] + 1.0f);
    if ((i & 31) == 0) g_dinv[n] = di;
    float w = di * di;
    float4 v = reinterpret_cast<const float4*>(g_h)[i];
    v.x *= w; v.y *= w; v.z *= w; v.w *= w;
    reinterpret_cast<float4*>(g_agg)[i] = v;
}

// ---------------------------------------------------------------------------
// Edge scatter: agg[dst] += dinv[src]*dinv[dst] * h[src].  Warp per edge.
// ---------------------------------------------------------------------------
__global__ void k_scatter(const int* __restrict__ src, const int* __restrict__ dst) {
    int gtid = blockIdx.x * blockDim.x + threadIdx.x;
    int e = gtid >> 5;
    if (e >= EE) return;
    int lane = gtid & 31;
    int s = __ldg(&src[e]);
    int d = __ldg(&dst[e]);
    float w = g_dinv[s] * g_dinv[d];
    float4 v = reinterpret_cast<const float4*>(g_h + (size_t)s * HH)[lane];
    float* ap = g_agg + (size_t)d * HH + lane * 4;
    atomicAdd(ap + 0, w * v.x);
    atomicAdd(ap + 1, w * v.y);
    atomicAdd(ap + 2, w * v.z);
    atomicAdd(ap + 3, w * v.w);
}

// ---------------------------------------------------------------------------
// Fused: hx = relu(agg + b1); logits = hx@Wp + bp; s = softmax(logits);
// write s; accumulate x_pool = S^T hx, ss = S^T S, den = sum(deg*||s||^2).
// Warp per node.
// ---------------------------------------------------------------------------
__global__ void k_s(const float* __restrict__ b1, const float* __restrict__ Wp,
                    const float* __restrict__ bp, float* __restrict__ sout) {
    __shared__ float Wps[HH * KK];
    __shared__ float b1s[HH];
    __shared__ float bps[KK];
    __shared__ float xps[KK * HH];
    __shared__ float svs[8][12];
    for (int i = threadIdx.x; i < HH * KK; i += blockDim.x) { Wps[i] = Wp[i]; xps[i] = 0.f; }
    if (threadIdx.x < HH) b1s[threadIdx.x] = b1[threadIdx.x];
    if (threadIdx.x < KK) bps[threadIdx.x] = bp[threadIdx.x];
    __syncthreads();

    const int lane = threadIdx.x & 31, warp = threadIdx.x >> 5;
    const int gw = blockIdx.x * 8 + warp, nw = gridDim.x * 8;
    const int i1 = lane + 32, i2 = lane + 64;
    const int k0 = lane / 9, l0 = lane % 9;
    const int k1 = i1 / 9, l1 = i1 % 9;
    const int k2 = i2 / 9, l2 = i2 % 9;

    float bl[4];
#pragma unroll
    for (int j = 0; j < 4; j++) bl[j] = b1s[lane * 4 + j];

    float acc[KK][4];
#pragma unroll
    for (int k = 0; k < KK; k++)
#pragma unroll
        for (int j = 0; j < 4; j++) acc[k][j] = 0.f;
    float ssa0 = 0.f, ssa1 = 0.f, ssa2 = 0.f, dena = 0.f;

    for (int n = gw; n < NN; n += nw) {
        float4 a = reinterpret_cast<const float4*>(g_agg + (size_t)n * HH)[lane];
        float v[4];
        v[0] = fmaxf(a.x + bl[0], 0.f);
        v[1] = fmaxf(a.y + bl[1], 0.f);
        v[2] = fmaxf(a.z + bl[2], 0.f);
        v[3] = fmaxf(a.w + bl[3], 0.f);

        float p[KK];
#pragma unroll
        for (int k = 0; k < KK; k++) p[k] = 0.f;
#pragma unroll
        for (int j = 0; j < 4; j++) {
            const float* w = &Wps[(lane * 4 + j) * KK];
#pragma unroll
            for (int k = 0; k < KK; k++) p[k] += v[j] * w[k];
        }
#pragma unroll
        for (int k = 0; k < KK; k++) {
            p[k] += __shfl_xor_sync(FULL, p[k], 16);
            p[k] += __shfl_xor_sync(FULL, p[k], 8);
            p[k] += __shfl_xor_sync(FULL, p[k], 4);
            p[k] += __shfl_xor_sync(FULL, p[k], 2);
            p[k] += __shfl_xor_sync(FULL, p[k], 1);
            p[k] += bps[k];
        }
        // softmax over K=9 (replicated in every lane)
        float m = p[0];
#pragma unroll
        for (int k = 1; k < KK; k++) m = fmaxf(m, p[k]);
        float sum = 0.f;
#pragma unroll
        for (int k = 0; k < KK; k++) { p[k] = __expf(p[k] - m); sum += p[k]; }
        float inv = 1.f / sum;
#pragma unroll
        for (int k = 0; k < KK; k++) p[k] *= inv;

        if (lane == 0) {
#pragma unroll
            for (int k = 0; k < KK; k++) {
                sout[(size_t)n * KK + k] = p[k];
                svs[warp][k] = p[k];
            }
            float s2 = 0.f;
#pragma unroll
            for (int k = 0; k < KK; k++) s2 += p[k] * p[k];
            dena += g_deg[n] * s2;
        }
        __syncwarp();
        ssa0 += svs[warp][k0] * svs[warp][l0];
        ssa1 += svs[warp][k1] * svs[warp][l1];
        if (i2 < 81) ssa2 += svs[warp][k2] * svs[warp][l2];
        __syncwarp();

#pragma unroll
        for (int k = 0; k < KK; k++) {
#pragma unroll
            for (int j = 0; j < 4; j++) acc[k][j] += p[k] * v[j];
        }
    }

    atomicAdd(&g_ss[lane], ssa0);
    atomicAdd(&g_ss[i1], ssa1);
    if (i2 < 81) atomicAdd(&g_ss[i2], ssa2);
    if (lane == 0) atomicAdd(&g_den[0], dena);
#pragma unroll
    for (int k = 0; k < KK; k++)
#pragma unroll
        for (int j = 0; j < 4; j++)
            atomicAdd(&xps[k * HH + lane * 4 + j], acc[k][j]);
    __syncthreads();
    for (int i = threadIdx.x; i < KK * HH; i += blockDim.x)
        atomicAdd(&g_xpool[i], xps[i]);
}

// ---------------------------------------------------------------------------
// out_adj[k][l] = sum_e s[src_e][k] * s[dst_e][l].  Warp per edge (strided),
// 81 entries spread 3-per-lane via shuffle broadcast.
// ---------------------------------------------------------------------------
__global__ void k_outadj(const int* __restrict__ src, const int* __restrict__ dst,
                         const float* __restrict__ sout) {
    const int lane = threadIdx.x & 31, warp = threadIdx.x >> 5;
    const int gw = blockIdx.x * 8 + warp, nw = gridDim.x * 8;
    const int i1 = lane + 32, i2 = lane + 64;
    const int k0 = lane / 9, l0 = lane % 9;
    const int k1 = i1 / 9, l1 = i1 % 9;
    const int k2 = i2 / 9, l2 = i2 % 9;
    float a0 = 0.f, a1 = 0.f, a2 = 0.f;
    for (int e = gw; e < EE; e += nw) {
        int s = __ldg(&src[e]);
        int d = __ldg(&dst[e]);
        float val = 0.f;
        if (lane < 9)       val = sout[(size_t)s * KK + lane];
        else if (lane < 18) val = sout[(size_t)d * KK + (lane - 9)];
        float x0 = __shfl_sync(FULL, val, k0), y0 = __shfl_sync(FULL, val, 9 + l0);
        float x1 = __shfl_sync(FULL, val, k1), y1 = __shfl_sync(FULL, val, 9 + l1);
        float x2 = __shfl_sync(FULL, val, k2), y2 = __shfl_sync(FULL, val, 9 + l2);
        a0 += x0 * y0;
        a1 += x1 * y1;
        if (i2 < 81) a2 += x2 * y2;
    }
    atomicAdd(&g_outadj[lane], a0);
    atomicAdd(&g_outadj[i1], a1);
    if (i2 < 81) atomicAdd(&g_outadj[i2], a2);
}

// ---------------------------------------------------------------------------
// Finalize: mc, o, normalized out_adj, log_softmax(x_pool). Single block.
// ---------------------------------------------------------------------------
__global__ void k_final(float* __restrict__ out) {
    __shared__ float oas[81], sss[81], dis[9];
    int t = threadIdx.x;
    if (t < 81) { oas[t] = g_outadj[t]; sss[t] = g_ss[t]; }
    __syncthreads();
    if (t == 0) {
        float tr = 0.f;
        for (int k = 0; k < KK; k++) tr += oas[k * KK + k];
        out[OFF_MC] = -(tr / (g_den[0] + 1e-15f));
        float n2 = 0.f;
        for (int i = 0; i < 81; i++) n2 += sss[i] * sss[i];
        float nf = sqrtf(n2);
        float o2 = 0.f;
        for (int k = 0; k < KK; k++)
            for (int l = 0; l < KK; l++) {
                float v = sss[k * KK + l] / nf - ((k == l) ? (1.f / 3.f) : 0.f);
                o2 += v * v;
            }
        out[OFF_O] = sqrtf(o2);
    }
    if (t < KK) {
        float dsum = 0.f;
        for (int l = 0; l < KK; l++)
            if (l != t) dsum += oas[t * KK + l];
        dis[t] = rsqrtf(dsum + 1e-15f);
    }
    __syncthreads();
    if (t < 81) {
        int k = t / KK, l = t % KK;
        out[OFF_OA + t] = (k == l) ? 0.f : dis[k] * oas[t] * dis[l];
    }
    // log_softmax over H per cluster row
    int lane = t & 31, warp = t >> 5;
    for (int k = warp; k < KK; k += 4) {
        float v[4], m = -1e30f;
#pragma unroll
        for (int j = 0; j < 4; j++) {
            v[j] = g_xpool[k * HH + lane + 32 * j];
            m = fmaxf(m, v[j]);
        }
        for (int off = 16; off > 0; off >>= 1) m = fmaxf(m, __shfl_xor_sync(FULL, m, off));
        float se = 0.f;
#pragma unroll
        for (int j = 0; j < 4; j++) se += expf(v[j] - m);
        for (int off = 16; off > 0; off >>= 1) se += __shfl_xor_sync(FULL, se, off);
        float lse = logf(se) + m;
#pragma unroll
        for (int j = 0; j < 4; j++) out[OFF_OUT + k * HH + lane + 32 * j] = v[j] - lse;
    }
}

// ---------------------------------------------------------------------------
extern "C" void kernel_launch(void* const* d_in, const int* in_sizes, int n_in,
                              void* d_out, int out_size) {
    const float* x  = (const float*)d_in[0];
    const int*   ei = (const int*)d_in[1];
    // d_in[2] = batch (all zeros, single graph) — unused
    const float* W1 = (const float*)d_in[3];
    const float* b1 = (const float*)d_in[4];
    const float* Wp = (const float*)d_in[5];
    const float* bp = (const float*)d_in[6];
    float* out = (float*)d_out;
    const int* src = ei;
    const int* dst = ei + EE;

    k_zero<<<(NN + 255) / 256, 256>>>();
    k_gemm1<<<592, 256>>>(x, W1);
    k_deg<<<(EE + 255) / 256, 256>>>(dst);
    k_init<<<(NN * HH / 4 + 255) / 256, 256>>>();
    k_scatter<<<(EE * 32) / 256, 256>>>(src, dst);
    k_s<<<592, 256>>>(b1, Wp, bp, out + OFF_S);
    k_outadj<<<592, 256>>>(src, dst, out + OFF_S);
    k_final<<<1, 128>>>(out);
}

// round 4
// speedup vs baseline: 1.3002x; 1.3002x over previous
#include <cuda_runtime.h>

#define NN 100000
#define EE 800000
#define INC 64
#define HH 128
#define KK 9
#define FULL 0xffffffffu

#define OFF_OUT 0
#define OFF_MC  1152
#define OFF_O   1153
#define OFF_S   1154
#define OFF_OA  901154

// Scratch (static device globals — allocation-free)
__device__ __align__(16) float g_h[NN * HH];    // hs = dinv[n] * (x @ W1)
__device__ __align__(16) float g_agg[NN * HH];  // init hs[n], += hs[src] over edges
__device__ float g_deg[NN];                     // in-degree (no self loop)
__device__ float g_xpool[KK * HH];
__device__ float g_outadj[KK * KK];
__device__ float g_ss[KK * KK];
__device__ float g_den[1];

// ---------------------------------------------------------------------------
// Zero accumulators (runs every call — graph replays)
// ---------------------------------------------------------------------------
__global__ void k_zero() {
    int i = blockIdx.x * blockDim.x + threadIdx.x;
    if (i < NN) g_deg[i] = 0.f;
    if (i < KK * HH) g_xpool[i] = 0.f;
    if (i < KK * KK) { g_outadj[i] = 0.f; g_ss[i] = 0.f; }
    if (i == 0) g_den[0] = 0.f;
}

// ---------------------------------------------------------------------------
// In-degree at dst (no self loops)
// ---------------------------------------------------------------------------
__global__ void k_deg(const int* __restrict__ dst) {
    int e = blockIdx.x * blockDim.x + threadIdx.x;
    if (e < EE) atomicAdd(&g_deg[dst[e]], 1.0f);
}

// ---------------------------------------------------------------------------
// hs = dinv[n]*(x @ W1) -> g_h AND g_agg (self-loop seed). Warp per row.
// ---------------------------------------------------------------------------
__global__ void k_gemm1(const float* __restrict__ x, const float* __restrict__ W1) {
    __shared__ float Ws[INC * HH];  // 32 KB
    for (int i = threadIdx.x; i < INC * HH; i += blockDim.x) Ws[i] = W1[i];
    __syncthreads();
    const int lane = threadIdx.x & 31, warp = threadIdx.x >> 5;
    const int nw = (blockDim.x >> 5) * gridDim.x;
    for (int n = blockIdx.x * (blockDim.x >> 5) + warp; n < NN; n += nw) {
        float xv0 = x[(size_t)n * INC + lane];
        float xv1 = x[(size_t)n * INC + 32 + lane];
        float a0 = 0.f, a1 = 0.f, a2 = 0.f, a3 = 0.f;
#pragma unroll
        for (int k = 0; k < INC; k++) {
            float xk = __shfl_sync(FULL, (k < 32) ? xv0 : xv1, k & 31);
            const float* w = Ws + k * HH + lane;
            a0 += xk * w[0]; a1 += xk * w[32]; a2 += xk * w[64]; a3 += xk * w[96];
        }
        float di = rsqrtf(g_deg[n] + 1.0f);
        a0 *= di; a1 *= di; a2 *= di; a3 *= di;
        float* hp = g_h + (size_t)n * HH + lane;
        hp[0] = a0; hp[32] = a1; hp[64] = a2; hp[96] = a3;
        float* ap = g_agg + (size_t)n * HH + lane;
        ap[0] = a0; ap[32] = a1; ap[64] = a2; ap[96] = a3;
    }
}

// ---------------------------------------------------------------------------
// Edge scatter: agg[dst] += hs[src] (unweighted; dinv[d] applied in k_s).
// Warp per edge, one red.global.add.v4.f32 per lane (16B vector reduction).
// ---------------------------------------------------------------------------
__global__ void k_scatter(const int* __restrict__ src, const int* __restrict__ dst) {
    int gtid = blockIdx.x * blockDim.x + threadIdx.x;
    int e = gtid >> 5;
    if (e >= EE) return;
    int lane = gtid & 31;
    int s = __ldg(&src[e]);
    int d = __ldg(&dst[e]);
    float4 v = reinterpret_cast<const float4*>(g_h + (size_t)s * HH)[lane];
    float* ap = g_agg + (size_t)d * HH + lane * 4;
    asm volatile("red.global.add.v4.f32 [%0], {%1, %2, %3, %4};"
                 :: "l"(ap), "f"(v.x), "f"(v.y), "f"(v.z), "f"(v.w)
                 : "memory");
}

// ---------------------------------------------------------------------------
// Fused: hx = relu(dinv[n]*agg + b1); s = softmax(hx@Wp + bp);
// write s; accumulate x_pool = S^T hx, ss = S^T S, den = sum(deg*||s||^2).
// Warp per node.
// ---------------------------------------------------------------------------
__global__ void k_s(const float* __restrict__ b1, const float* __restrict__ Wp,
                    const float* __restrict__ bp, float* __restrict__ sout) {
    __shared__ float Wps[HH * KK];
    __shared__ float b1s[HH];
    __shared__ float bps[KK];
    __shared__ float xps[KK * HH];
    __shared__ float svs[8][12];
    for (int i = threadIdx.x; i < HH * KK; i += blockDim.x) { Wps[i] = Wp[i]; xps[i] = 0.f; }
    if (threadIdx.x < HH) b1s[threadIdx.x] = b1[threadIdx.x];
    if (threadIdx.x < KK) bps[threadIdx.x] = bp[threadIdx.x];
    __syncthreads();

    const int lane = threadIdx.x & 31, warp = threadIdx.x >> 5;
    const int gw = blockIdx.x * 8 + warp, nw = gridDim.x * 8;
    const int i1 = lane + 32, i2 = lane + 64;
    const int k0 = lane / 9, l0 = lane % 9;
    const int k1 = i1 / 9, l1 = i1 % 9;
    const int k2 = i2 / 9, l2 = i2 % 9;

    float bl[4];
#pragma unroll
    for (int j = 0; j < 4; j++) bl[j] = b1s[lane * 4 + j];

    float acc[KK][4];
#pragma unroll
    for (int k = 0; k < KK; k++)
#pragma unroll
        for (int j = 0; j < 4; j++) acc[k][j] = 0.f;
    float ssa0 = 0.f, ssa1 = 0.f, ssa2 = 0.f, dena = 0.f;

    for (int n = gw; n < NN; n += nw) {
        float deg = g_deg[n];
        float di = rsqrtf(deg + 1.0f);
        float4 a = reinterpret_cast<const float4*>(g_agg + (size_t)n * HH)[lane];
        float v[4];
        v[0] = fmaxf(di * a.x + bl[0], 0.f);
        v[1] = fmaxf(di * a.y + bl[1], 0.f);
        v[2] = fmaxf(di * a.z + bl[2], 0.f);
        v[3] = fmaxf(di * a.w + bl[3], 0.f);

        float p[KK];
#pragma unroll
        for (int k = 0; k < KK; k++) p[k] = 0.f;
#pragma unroll
        for (int j = 0; j < 4; j++) {
            const float* w = &Wps[(lane * 4 + j) * KK];
#pragma unroll
            for (int k = 0; k < KK; k++) p[k] += v[j] * w[k];
        }
#pragma unroll
        for (int k = 0; k < KK; k++) {
            p[k] += __shfl_xor_sync(FULL, p[k], 16);
            p[k] += __shfl_xor_sync(FULL, p[k], 8);
            p[k] += __shfl_xor_sync(FULL, p[k], 4);
            p[k] += __shfl_xor_sync(FULL, p[k], 2);
            p[k] += __shfl_xor_sync(FULL, p[k], 1);
            p[k] += bps[k];
        }
        // softmax over K=9 (replicated in every lane)
        float m = p[0];
#pragma unroll
        for (int k = 1; k < KK; k++) m = fmaxf(m, p[k]);
        float sum = 0.f;
#pragma unroll
        for (int k = 0; k < KK; k++) { p[k] = __expf(p[k] - m); sum += p[k]; }
        float inv = 1.f / sum;
#pragma unroll
        for (int k = 0; k < KK; k++) p[k] *= inv;

        if (lane == 0) {
#pragma unroll
            for (int k = 0; k < KK; k++) {
                sout[(size_t)n * KK + k] = p[k];
                svs[warp][k] = p[k];
            }
            float s2 = 0.f;
#pragma unroll
            for (int k = 0; k < KK; k++) s2 += p[k] * p[k];
            dena += deg * s2;
        }
        __syncwarp();
        ssa0 += svs[warp][k0] * svs[warp][l0];
        ssa1 += svs[warp][k1] * svs[warp][l1];
        if (i2 < 81) ssa2 += svs[warp][k2] * svs[warp][l2];
        __syncwarp();

#pragma unroll
        for (int k = 0; k < KK; k++) {
#pragma unroll
            for (int j = 0; j < 4; j++) acc[k][j] += p[k] * v[j];
        }
    }

    atomicAdd(&g_ss[lane], ssa0);
    atomicAdd(&g_ss[i1], ssa1);
    if (i2 < 81) atomicAdd(&g_ss[i2], ssa2);
    if (lane == 0) atomicAdd(&g_den[0], dena);
#pragma unroll
    for (int k = 0; k < KK; k++)
#pragma unroll
        for (int j = 0; j < 4; j++)
            atomicAdd(&xps[k * HH + lane * 4 + j], acc[k][j]);
    __syncthreads();
    for (int i = threadIdx.x; i < KK * HH; i += blockDim.x)
        atomicAdd(&g_xpool[i], xps[i]);
}

// ---------------------------------------------------------------------------
// out_adj[k][l] = sum_e s[src_e][k] * s[dst_e][l].  Warp per edge (strided),
// 81 entries spread 3-per-lane via shuffle broadcast.
// ---------------------------------------------------------------------------
__global__ void k_outadj(const int* __restrict__ src, const int* __restrict__ dst,
                         const float* __restrict__ sout) {
    const int lane = threadIdx.x & 31, warp = threadIdx.x >> 5;
    const int gw = blockIdx.x * 8 + warp, nw = gridDim.x * 8;
    const int i1 = lane + 32, i2 = lane + 64;
    const int k0 = lane / 9, l0 = lane % 9;
    const int k1 = i1 / 9, l1 = i1 % 9;
    const int k2 = i2 / 9, l2 = i2 % 9;
    float a0 = 0.f, a1 = 0.f, a2 = 0.f;
    for (int e = gw; e < EE; e += nw) {
        int s = __ldg(&src[e]);
        int d = __ldg(&dst[e]);
        float val = 0.f;
        if (lane < 9)       val = sout[(size_t)s * KK + lane];
        else if (lane < 18) val = sout[(size_t)d * KK + (lane - 9)];
        float x0 = __shfl_sync(FULL, val, k0), y0 = __shfl_sync(FULL, val, 9 + l0);
        float x1 = __shfl_sync(FULL, val, k1), y1 = __shfl_sync(FULL, val, 9 + l1);
        float x2 = __shfl_sync(FULL, val, k2), y2 = __shfl_sync(FULL, val, 9 + l2);
        a0 += x0 * y0;
        a1 += x1 * y1;
        if (i2 < 81) a2 += x2 * y2;
    }
    atomicAdd(&g_outadj[lane], a0);
    atomicAdd(&g_outadj[i1], a1);
    if (i2 < 81) atomicAdd(&g_outadj[i2], a2);
}

// ---------------------------------------------------------------------------
// Finalize: mc, o, normalized out_adj, log_softmax(x_pool). Single block.
// ---------------------------------------------------------------------------
__global__ void k_final(float* __restrict__ out) {
    __shared__ float oas[81], sss[81], dis[9];
    int t = threadIdx.x;
    if (t < 81) { oas[t] = g_outadj[t]; sss[t] = g_ss[t]; }
    __syncthreads();
    if (t == 0) {
        float tr = 0.f;
        for (int k = 0; k < KK; k++) tr += oas[k * KK + k];
        out[OFF_MC] = -(tr / (g_den[0] + 1e-15f));
        float n2 = 0.f;
        for (int i = 0; i < 81; i++) n2 += sss[i] * sss[i];
        float nf = sqrtf(n2);
        float o2 = 0.f;
        for (int k = 0; k < KK; k++)
            for (int l = 0; l < KK; l++) {
                float v = sss[k * KK + l] / nf - ((k == l) ? (1.f / 3.f) : 0.f);
                o2 += v * v;
            }
        out[OFF_O] = sqrtf(o2);
    }
    if (t < KK) {
        float dsum = 0.f;
        for (int l = 0; l < KK; l++)
            if (l != t) dsum += oas[t * KK + l];
        dis[t] = rsqrtf(dsum + 1e-15f);
    }
    __syncthreads();
    if (t < 81) {
        int k = t / KK, l = t % KK;
        out[OFF_OA + t] = (k == l) ? 0.f : dis[k] * oas[t] * dis[l];
    }
    // log_softmax over H per cluster row
    int lane = t & 31, warp = t >> 5;
    for (int k = warp; k < KK; k += 4) {
        float v[4], m = -1e30f;
#pragma unroll
        for (int j = 0; j < 4; j++) {
            v[j] = g_xpool[k * HH + lane + 32 * j];
            m = fmaxf(m, v[j]);
        }
        for (int off = 16; off > 0; off >>= 1) m = fmaxf(m, __shfl_xor_sync(FULL, m, off));
        float se = 0.f;
#pragma unroll
        for (int j = 0; j < 4; j++) se += expf(v[j] - m);
        for (int off = 16; off > 0; off >>= 1) se += __shfl_xor_sync(FULL, se, off);
        float lse = logf(se) + m;
#pragma unroll
        for (int j = 0; j < 4; j++) out[OFF_OUT + k * HH + lane + 32 * j] = v[j] - lse;
    }
}

// ---------------------------------------------------------------------------
extern "C" void kernel_launch(void* const* d_in, const int* in_sizes, int n_in,
                              void* d_out, int out_size) {
    const float* x  = (const float*)d_in[0];
    const int*   ei = (const int*)d_in[1];
    // d_in[2] = batch (all zeros, single graph) — unused
    const float* W1 = (const float*)d_in[3];
    const float* b1 = (const float*)d_in[4];
    const float* Wp = (const float*)d_in[5];
    const float* bp = (const float*)d_in[6];
    float* out = (float*)d_out;
    const int* src = ei;
    const int* dst = ei + EE;

    k_zero<<<(NN + 255) / 256, 256>>>();
    k_deg<<<(EE + 255) / 256, 256>>>(dst);
    k_gemm1<<<592, 256>>>(x, W1);
    k_scatter<<<(EE * 32) / 256, 256>>>(src, dst);
    k_s<<<592, 256>>>(b1, Wp, bp, out + OFF_S);
    k_outadj<<<592, 256>>>(src, dst, out + OFF_S);
    k_final<<<1, 128>>>(out);
}

// round 6
// speedup vs baseline: 1.8198x; 1.3996x over previous
#include <cuda_runtime.h>

#define NN 100000
#define EE 800000
#define INC 64
#define HH 128
#define KK 9
#define FULL 0xffffffffu

#define OFF_OUT 0
#define OFF_MC  1152
#define OFF_O   1153
#define OFF_S   1154
#define OFF_OA  901154

// Scratch (static device globals — allocation-free)
__device__ __align__(16) float g_xs[NN * INC];    // dinv[n] * x[n]
__device__ __align__(16) float g_aggx[NN * INC];  // xs[n] + sum xs[src]
__device__ float g_deg[NN];
__device__ float g_xpool[KK * HH];
__device__ float g_outadj[KK * KK];
__device__ float g_ss[KK * KK];
__device__ float g_den[1];

// ---------------------------------------------------------------------------
// Zero accumulators (runs every call — graph replays)
// ---------------------------------------------------------------------------
__global__ void k_zero() {
    int i = blockIdx.x * blockDim.x + threadIdx.x;
    if (i < NN) g_deg[i] = 0.f;
    if (i < KK * HH) g_xpool[i] = 0.f;
    if (i < KK * KK) { g_outadj[i] = 0.f; g_ss[i] = 0.f; }
    if (i == 0) g_den[0] = 0.f;
}

// ---------------------------------------------------------------------------
// In-degree at dst (no self loops)
// ---------------------------------------------------------------------------
__global__ void k_deg(const int* __restrict__ dst) {
    int e = blockIdx.x * blockDim.x + threadIdx.x;
    if (e < EE) atomicAdd(&g_deg[dst[e]], 1.0f);
}

// ---------------------------------------------------------------------------
// xs = dinv[n]*x[n]; aggx seeded with xs (self-loop term). float4 per thread.
// ---------------------------------------------------------------------------
__global__ void k_scale(const float* __restrict__ x) {
    int i = blockIdx.x * blockDim.x + threadIdx.x;  // float4 index, 16 per row
    if (i >= NN * 16) return;
    int n = i >> 4;
    float di = rsqrtf(g_deg[n] + 1.0f);
    float4 v = reinterpret_cast<const float4*>(x)[i];
    v.x *= di; v.y *= di; v.z *= di; v.w *= di;
    reinterpret_cast<float4*>(g_xs)[i] = v;
    reinterpret_cast<float4*>(g_aggx)[i] = v;
}

// ---------------------------------------------------------------------------
// Edge scatter on x-space: aggx[dst] += xs[src].  Half-warp (16 lanes) per
// edge, one red.global.add.v4.f32 per lane.
// ---------------------------------------------------------------------------
__global__ void k_scatter(const int* __restrict__ src, const int* __restrict__ dst) {
    int gtid = blockIdx.x * blockDim.x + threadIdx.x;
    int e = gtid >> 4;
    if (e >= EE) return;
    int l = gtid & 15;
    int s = __ldg(&src[e]);
    int d = __ldg(&dst[e]);
    float4 v = reinterpret_cast<const float4*>(g_xs)[s * 16 + l];
    float* ap = g_aggx + (size_t)d * INC + l * 4;
    asm volatile("red.global.add.v4.f32 [%0], {%1, %2, %3, %4};"
                 :: "l"(ap), "f"(v.x), "f"(v.y), "f"(v.z), "f"(v.w)
                 : "memory");
}

// ---------------------------------------------------------------------------
// Fused: hx = relu((dinv*aggx)@W1 + b1); s = softmax(hx@Wp + bp);
// write s; accumulate x_pool, ss, den.
// Warp processes 4 nodes per iteration (W1 smem reads amortized 4x).
// NN % 4 == 0, so no per-node guards needed.
// ---------------------------------------------------------------------------
__global__ void __launch_bounds__(256) k_s(
        const float* __restrict__ W1, const float* __restrict__ b1,
        const float* __restrict__ Wp, const float* __restrict__ bp,
        float* __restrict__ sout) {
    __shared__ float Ws[INC * HH];     // 32 KB, read as float4
    __shared__ float Wp12[HH * 12];    // Wp padded to 12 cols
    __shared__ float b1s[HH];
    __shared__ float bps[KK];
    __shared__ float xps[KK * HH];
    __shared__ float svs[8][12];
    for (int i = threadIdx.x; i < INC * HH; i += blockDim.x) Ws[i] = W1[i];
    for (int i = threadIdx.x; i < HH * 12; i += blockDim.x) {
        int r = i / 12, c = i % 12;
        Wp12[i] = (c < KK) ? Wp[r * KK + c] : 0.f;
    }
    for (int i = threadIdx.x; i < KK * HH; i += blockDim.x) xps[i] = 0.f;
    if (threadIdx.x < HH) b1s[threadIdx.x] = b1[threadIdx.x];
    if (threadIdx.x < KK) bps[threadIdx.x] = bp[threadIdx.x];
    __syncthreads();

    const int lane = threadIdx.x & 31, warp = threadIdx.x >> 5;
    const int gw = blockIdx.x * 8 + warp, nw = gridDim.x * 8;
    const int i1 = lane + 32, i2 = lane + 64;
    const int k0 = lane / 9, l0 = lane % 9;
    const int k1 = i1 / 9, l1 = i1 % 9;
    const int k2 = i2 / 9, l2 = i2 % 9;
    const float4* Ws4 = reinterpret_cast<const float4*>(Ws);
    const float4* Wp4 = reinterpret_cast<const float4*>(Wp12);
    const float2* ax2 = reinterpret_cast<const float2*>(g_aggx);

    float4 bl = reinterpret_cast<const float4*>(b1s)[lane];

    float acc[KK][4];
#pragma unroll
    for (int k = 0; k < KK; k++)
#pragma unroll
        for (int j = 0; j < 4; j++) acc[k][j] = 0.f;
    float ssa0 = 0.f, ssa1 = 0.f, ssa2 = 0.f, dena = 0.f;

    for (int g = gw; g * 4 < NN; g += nw) {
        const int base = g * 4;
        // load + dinv-scale 4 rows of aggx (2 floats/lane each)
        float2 xv[4];
        float degv[4];
#pragma unroll
        for (int nn = 0; nn < 4; nn++) {
            degv[nn] = g_deg[base + nn];
            float di = rsqrtf(degv[nn] + 1.0f);
            float2 t = ax2[(size_t)(base + nn) * 32 + lane];
            xv[nn].x = t.x * di; xv[nn].y = t.y * di;
        }
        // GEMM: 4 nodes x 4 cols per lane over K=64
        float4 ga[4];
#pragma unroll
        for (int nn = 0; nn < 4; nn++) ga[nn] = make_float4(0.f, 0.f, 0.f, 0.f);
#pragma unroll
        for (int k = 0; k < INC; k++) {
            float4 w = Ws4[k * 32 + lane];
#pragma unroll
            for (int nn = 0; nn < 4; nn++) {
                float xk = __shfl_sync(FULL, (k & 1) ? xv[nn].y : xv[nn].x, k >> 1);
                ga[nn].x += xk * w.x; ga[nn].y += xk * w.y;
                ga[nn].z += xk * w.z; ga[nn].w += xk * w.w;
            }
        }
        // epilogue per node
#pragma unroll
        for (int nn = 0; nn < 4; nn++) {
            const int n = base + nn;
            float v[4];
            v[0] = fmaxf(ga[nn].x + bl.x, 0.f);
            v[1] = fmaxf(ga[nn].y + bl.y, 0.f);
            v[2] = fmaxf(ga[nn].z + bl.z, 0.f);
            v[3] = fmaxf(ga[nn].w + bl.w, 0.f);

            float4 p4[3];
#pragma unroll
            for (int q = 0; q < 3; q++) p4[q] = make_float4(0.f, 0.f, 0.f, 0.f);
#pragma unroll
            for (int j = 0; j < 4; j++) {
                const int r = (lane * 4 + j) * 3;
#pragma unroll
                for (int q = 0; q < 3; q++) {
                    float4 w = Wp4[r + q];
                    p4[q].x += v[j] * w.x; p4[q].y += v[j] * w.y;
                    p4[q].z += v[j] * w.z; p4[q].w += v[j] * w.w;
                }
            }
            float p[KK] = {p4[0].x, p4[0].y, p4[0].z, p4[0].w,
                           p4[1].x, p4[1].y, p4[1].z, p4[1].w, p4[2].x};
#pragma unroll
            for (int k = 0; k < KK; k++) {
                p[k] += __shfl_xor_sync(FULL, p[k], 16);
                p[k] += __shfl_xor_sync(FULL, p[k], 8);
                p[k] += __shfl_xor_sync(FULL, p[k], 4);
                p[k] += __shfl_xor_sync(FULL, p[k], 2);
                p[k] += __shfl_xor_sync(FULL, p[k], 1);
                p[k] += bps[k];
            }
            // softmax over K=9 (replicated in every lane)
            float m = p[0];
#pragma unroll
            for (int k = 1; k < KK; k++) m = fmaxf(m, p[k]);
            float sum = 0.f;
#pragma unroll
            for (int k = 0; k < KK; k++) { p[k] = __expf(p[k] - m); sum += p[k]; }
            float inv = 1.f / sum;
#pragma unroll
            for (int k = 0; k < KK; k++) p[k] *= inv;

            if (lane == 0) {
#pragma unroll
                for (int k = 0; k < KK; k++) {
                    sout[(size_t)n * KK + k] = p[k];
                    svs[warp][k] = p[k];
                }
                float s2 = 0.f;
#pragma unroll
                for (int k = 0; k < KK; k++) s2 += p[k] * p[k];
                dena += degv[nn] * s2;
            }
            __syncwarp();
            ssa0 += svs[warp][k0] * svs[warp][l0];
            ssa1 += svs[warp][k1] * svs[warp][l1];
            if (i2 < 81) ssa2 += svs[warp][k2] * svs[warp][l2];
            __syncwarp();

#pragma unroll
            for (int k = 0; k < KK; k++) {
#pragma unroll
                for (int j = 0; j < 4; j++) acc[k][j] += p[k] * v[j];
            }
        }
    }

    atomicAdd(&g_ss[lane], ssa0);
    atomicAdd(&g_ss[i1], ssa1);
    if (i2 < 81) atomicAdd(&g_ss[i2], ssa2);
    if (lane == 0) atomicAdd(&g_den[0], dena);
#pragma unroll
    for (int k = 0; k < KK; k++)
#pragma unroll
        for (int j = 0; j < 4; j++)
            atomicAdd(&xps[k * HH + lane * 4 + j], acc[k][j]);
    __syncthreads();
    for (int i = threadIdx.x; i < KK * HH; i += blockDim.x)
        atomicAdd(&g_xpool[i], xps[i]);
}

// ---------------------------------------------------------------------------
// out_adj[k][l] = sum_e s[src_e][k] * s[dst_e][l].  Warp per edge (strided),
// 81 entries spread 3-per-lane via shuffle broadcast.  (R4-proven.)
// ---------------------------------------------------------------------------
__global__ void k_outadj(const int* __restrict__ src, const int* __restrict__ dst,
                         const float* __restrict__ sout) {
    const int lane = threadIdx.x & 31, warp = threadIdx.x >> 5;
    const int gw = blockIdx.x * 8 + warp, nw = gridDim.x * 8;
    const int i1 = lane + 32, i2 = lane + 64;
    const int k0 = lane / 9, l0 = lane % 9;
    const int k1 = i1 / 9, l1 = i1 % 9;
    const int k2 = i2 / 9, l2 = i2 % 9;
    float a0 = 0.f, a1 = 0.f, a2 = 0.f;
    for (int e = gw; e < EE; e += nw) {
        int s = __ldg(&src[e]);
        int d = __ldg(&dst[e]);
        float val = 0.f;
        if (lane < 9)       val = sout[(size_t)s * KK + lane];
        else if (lane < 18) val = sout[(size_t)d * KK + (lane - 9)];
        float x0 = __shfl_sync(FULL, val, k0), y0 = __shfl_sync(FULL, val, 9 + l0);
        float x1 = __shfl_sync(FULL, val, k1), y1 = __shfl_sync(FULL, val, 9 + l1);
        float x2 = __shfl_sync(FULL, val, k2), y2 = __shfl_sync(FULL, val, 9 + l2);
        a0 += x0 * y0;
        a1 += x1 * y1;
        if (i2 < 81) a2 += x2 * y2;
    }
    atomicAdd(&g_outadj[lane], a0);
    atomicAdd(&g_outadj[i1], a1);
    if (i2 < 81) atomicAdd(&g_outadj[i2], a2);
}

// ---------------------------------------------------------------------------
// Finalize: mc, o, normalized out_adj, log_softmax(x_pool). Single block.
// ---------------------------------------------------------------------------
__global__ void k_final(float* __restrict__ out) {
    __shared__ float oas[81], sss[81], dis[9];
    int t = threadIdx.x;
    if (t < 81) { oas[t] = g_outadj[t]; sss[t] = g_ss[t]; }
    __syncthreads();
    if (t == 0) {
        float tr = 0.f;
        for (int k = 0; k < KK; k++) tr += oas[k * KK + k];
        out[OFF_MC] = -(tr / (g_den[0] + 1e-15f));
        float n2 = 0.f;
        for (int i = 0; i < 81; i++) n2 += sss[i] * sss[i];
        float nf = sqrtf(n2);
        float o2 = 0.f;
        for (int k = 0; k < KK; k++)
            for (int l = 0; l < KK; l++) {
                float v = sss[k * KK + l] / nf - ((k == l) ? (1.f / 3.f) : 0.f);
                o2 += v * v;
            }
        out[OFF_O] = sqrtf(o2);
    }
    if (t < KK) {
        float dsum = 0.f;
        for (int l = 0; l < KK; l++)
            if (l != t) dsum += oas[t * KK + l];
        dis[t] = rsqrtf(dsum + 1e-15f);
    }
    __syncthreads();
    if (t < 81) {
        int k = t / KK, l = t % KK;
        out[OFF_OA + t] = (k == l) ? 0.f : dis[k] * oas[t] * dis[l];
    }
    // log_softmax over H per cluster row
    int lane = t & 31, warp = t >> 5;
    for (int k = warp; k < KK; k += 4) {
        float v[4], m = -1e30f;
#pragma unroll
        for (int j = 0; j < 4; j++) {
            v[j] = g_xpool[k * HH + lane + 32 * j];
            m = fmaxf(m, v[j]);
        }
        for (int off = 16; off > 0; off >>= 1) m = fmaxf(m, __shfl_xor_sync(FULL, m, off));
        float se = 0.f;
#pragma unroll
        for (int j = 0; j < 4; j++) se += expf(v[j] - m);
        for (int off = 16; off > 0; off >>= 1) se += __shfl_xor_sync(FULL, se, off);
        float lse = logf(se) + m;
#pragma unroll
        for (int j = 0; j < 4; j++) out[OFF_OUT + k * HH + lane + 32 * j] = v[j] - lse;
    }
}

// ---------------------------------------------------------------------------
extern "C" void kernel_launch(void* const* d_in, const int* in_sizes, int n_in,
                              void* d_out, int out_size) {
    const float* x  = (const float*)d_in[0];
    const int*   ei = (const int*)d_in[1];
    // d_in[2] = batch (all zeros, single graph) — unused
    const float* W1 = (const float*)d_in[3];
    const float* b1 = (const float*)d_in[4];
    const float* Wp = (const float*)d_in[5];
    const float* bp = (const float*)d_in[6];
    float* out = (float*)d_out;
    const int* src = ei;
    const int* dst = ei + EE;

    k_zero<<<(NN + 255) / 256, 256>>>();
    k_deg<<<(EE + 255) / 256, 256>>>(dst);
    k_scale<<<(NN * 16 + 255) / 256, 256>>>(x);
    k_scatter<<<(EE * 16) / 256, 256>>>(src, dst);
    k_s<<<592, 256>>>(W1, b1, Wp, bp, out + OFF_S);
    k_outadj<<<592, 256>>>(src, dst, out + OFF_S);
    k_final<<<1, 128>>>(out);
}